// round 2
// baseline (speedup 1.0000x reference)
#include <cuda_runtime.h>
#include <cuda_bf16.h>
#include <cstdint>

// ---------------- problem constants ----------------
constexpr int BB = 4;
constexpr int LL = 2048;
constexpr int DM = 1024;
constexpr int DI = 2048;      // d_inner
constexpr int DS = 16;        // d_state
constexpr int MR = BB * LL;   // 8192 rows
constexpr int NXZ = 2 * DI;   // 4096

// ---------------- scratch (device globals; no allocation allowed) ----------------
__device__ float g_xz[(size_t)MR * NXZ];       // 128 MB : [xi | z]
__device__ float g_xiconv[(size_t)MR * DI];    // 64 MB  : silu(conv(xi))
__device__ float g_dtraw[MR];                  // xd[:,0]
__device__ float g_Bc[MR * DS];                // xd[:,1:17]
__device__ float g_Cc[MR * DS];                // xd[:,17:33]
__device__ float g_dt[(size_t)MR * DI];        // 64 MB
__device__ float g_y[(size_t)MR * DI];         // 64 MB
__device__ float g_outpre[(size_t)MR * DI];    // 64 MB

// ============================================================================
// SGEMM NT: C[M,N] = A[M,K] * B[N,K]^T   (all row-major, fp32)
// 128x128 block tile, BK=16, 256 threads, 8x8 per thread with 4+4 split
// ============================================================================
template<int M, int N, int K>
__device__ __forceinline__ void sgemm_nt_body(const float* __restrict__ A,
                                              const float* __restrict__ B,
                                              float* __restrict__ C) {
    constexpr int BM = 128, BN = 128, BK = 16;
    __shared__ float As[BK][BM];
    __shared__ float Bs[BK][BN];

    const int tid = threadIdx.x;
    const int bm0 = blockIdx.y * BM;
    const int bn0 = blockIdx.x * BN;
    const int tx = tid & 15;       // 16 cols of threads
    const int ty = tid >> 4;       // 16 rows of threads

    float acc[8][8];
    #pragma unroll
    for (int i = 0; i < 8; i++)
        #pragma unroll
        for (int j = 0; j < 8; j++) acc[i][j] = 0.f;

    const float* Aptr = A + (size_t)bm0 * K;
    const float* Bptr = B + (size_t)bn0 * K;

    for (int k0 = 0; k0 < K; k0 += BK) {
        // load A tile (128x16) as 512 float4, 2 per thread, store transposed
        #pragma unroll
        for (int i = 0; i < 2; i++) {
            int f = tid + i * 256;
            int row = f >> 2;
            int kc = (f & 3) * 4;
            float4 v = *(const float4*)(Aptr + (size_t)row * K + k0 + kc);
            As[kc + 0][row] = v.x; As[kc + 1][row] = v.y;
            As[kc + 2][row] = v.z; As[kc + 3][row] = v.w;
        }
        #pragma unroll
        for (int i = 0; i < 2; i++) {
            int f = tid + i * 256;
            int row = f >> 2;
            int kc = (f & 3) * 4;
            float4 v = *(const float4*)(Bptr + (size_t)row * K + k0 + kc);
            Bs[kc + 0][row] = v.x; Bs[kc + 1][row] = v.y;
            Bs[kc + 2][row] = v.z; Bs[kc + 3][row] = v.w;
        }
        __syncthreads();

        #pragma unroll
        for (int kk = 0; kk < BK; kk++) {
            float a[8], b[8];
            // 4+4 split avoids smem bank conflicts on the 128-bit loads
            *(float4*)&a[0] = *(const float4*)&As[kk][ty * 4];
            *(float4*)&a[4] = *(const float4*)&As[kk][64 + ty * 4];
            *(float4*)&b[0] = *(const float4*)&Bs[kk][tx * 4];
            *(float4*)&b[4] = *(const float4*)&Bs[kk][64 + tx * 4];
            #pragma unroll
            for (int i = 0; i < 8; i++)
                #pragma unroll
                for (int j = 0; j < 8; j++)
                    acc[i][j] += a[i] * b[j];
        }
        __syncthreads();
    }

    // write back: rows {ty*4..+3, 64+ty*4..+3}, cols {tx*4..+3, 64+tx*4..+3}
    #pragma unroll
    for (int i = 0; i < 8; i++) {
        int row = bm0 + ((i < 4) ? (ty * 4 + i) : (64 + ty * 4 + i - 4));
        float* Crow = C + (size_t)row * N + bn0;
        *(float4*)(Crow + tx * 4)      = make_float4(acc[i][0], acc[i][1], acc[i][2], acc[i][3]);
        *(float4*)(Crow + 64 + tx * 4) = make_float4(acc[i][4], acc[i][5], acc[i][6], acc[i][7]);
    }
}

__global__ void __launch_bounds__(256) gemm_xz_kernel(const float* __restrict__ x,
                                                      const float* __restrict__ W_in) {
    sgemm_nt_body<MR, NXZ, DM>(x, W_in, g_xz);
}

__global__ void __launch_bounds__(256) gemm_out_kernel(const float* __restrict__ W_out,
                                                       float* __restrict__ out) {
    sgemm_nt_body<MR, DM, DI>(g_outpre, W_out, out);
}

// ============================================================================
// causal depthwise conv (k=4, pad left 3) + bias + silu
// ============================================================================
__global__ void __launch_bounds__(256) conv_silu_kernel(const float* __restrict__ conv_w,
                                                        const float* __restrict__ conv_b) {
    int idx = blockIdx.x * 256 + threadIdx.x;           // over MR*DI
    if (idx >= MR * DI) return;
    int c = idx & (DI - 1);
    int m = idx >> 11;          // DI = 2048
    int l = m & (LL - 1);

    float4 w4 = *(const float4*)(conv_w + c * 4);
    float w[4] = {w4.x, w4.y, w4.z, w4.w};
    const float* base = g_xz + (size_t)m * NXZ + c;     // xi part (cols [0,DI))
    float s = conv_b[c];
    #pragma unroll
    for (int t = 0; t < 4; t++) {
        int ll = l - 3 + t;
        if (ll >= 0) s += base[(size_t)(t - 3) * NXZ] * w[t];
    }
    // silu
    float sv = s / (1.f + expf(-s));
    g_xiconv[idx] = sv;
}

// ============================================================================
// xd = xi_conv @ W_x^T  (N=33).  4 rows per block; warp-per-output-column.
// ============================================================================
__global__ void __launch_bounds__(256) projx_kernel(const float* __restrict__ W_x) {
    __shared__ float xs[4][DI];
    const int m0 = blockIdx.x * 4;
    for (int i = threadIdx.x; i < 4 * DI; i += 256) {
        int r = i >> 11, c = i & (DI - 1);
        xs[r][c] = g_xiconv[(size_t)(m0 + r) * DI + c];
    }
    __syncthreads();

    const int warp = threadIdx.x >> 5;
    const int lane = threadIdx.x & 31;
    for (int n = warp; n < 2 * DS + 1; n += 8) {
        const float* w = W_x + n * DI;
        float a0 = 0.f, a1 = 0.f, a2 = 0.f, a3 = 0.f;
        for (int k = lane * 4; k < DI; k += 128) {
            float4 wv = *(const float4*)(w + k);
            float4 x0 = *(const float4*)&xs[0][k];
            float4 x1 = *(const float4*)&xs[1][k];
            float4 x2 = *(const float4*)&xs[2][k];
            float4 x3 = *(const float4*)&xs[3][k];
            a0 += wv.x * x0.x + wv.y * x0.y + wv.z * x0.z + wv.w * x0.w;
            a1 += wv.x * x1.x + wv.y * x1.y + wv.z * x1.z + wv.w * x1.w;
            a2 += wv.x * x2.x + wv.y * x2.y + wv.z * x2.z + wv.w * x2.w;
            a3 += wv.x * x3.x + wv.y * x3.y + wv.z * x3.z + wv.w * x3.w;
        }
        #pragma unroll
        for (int off = 16; off; off >>= 1) {
            a0 += __shfl_xor_sync(0xffffffffu, a0, off);
            a1 += __shfl_xor_sync(0xffffffffu, a1, off);
            a2 += __shfl_xor_sync(0xffffffffu, a2, off);
            a3 += __shfl_xor_sync(0xffffffffu, a3, off);
        }
        if (lane == 0) {
            float acc[4] = {a0, a1, a2, a3};
            #pragma unroll
            for (int r = 0; r < 4; r++) {
                int m = m0 + r;
                if (n == 0)            g_dtraw[m] = acc[r];
                else if (n < 1 + DS)   g_Bc[m * DS + (n - 1)] = acc[r];
                else                   g_Cc[m * DS + (n - 1 - DS)] = acc[r];
            }
        }
    }
}

// ============================================================================
// dt = clip(softplus(dtraw * W_dt[d] + b_dt[d]), 1e-4, 10)
// ============================================================================
__global__ void __launch_bounds__(256) dt_kernel(const float* __restrict__ W_dt,
                                                 const float* __restrict__ b_dt) {
    int idx = blockIdx.x * 256 + threadIdx.x;
    if (idx >= MR * DI) return;
    int d = idx & (DI - 1);
    int m = idx >> 11;
    float xx = g_dtraw[m] * W_dt[d] + b_dt[d];
    float sp = fmaxf(xx, 0.f) + log1pf(expf(-fabsf(xx)));   // stable softplus
    g_dt[idx] = fminf(fmaxf(sp, 1e-4f), 10.f);
}

// ============================================================================
// selective scan: 4 threads per (b,d) channel, 4 states each.
// grid (DI/32, BB), block 128
// ============================================================================
__global__ void __launch_bounds__(128) scan_kernel(const float* __restrict__ A_log) {
    const int sub  = threadIdx.x & 3;
    const int dloc = threadIdx.x >> 2;
    const int d    = blockIdx.x * 32 + dloc;
    const int b    = blockIdx.y;
    const int s0   = sub * 4;

    float Ac[4];
    #pragma unroll
    for (int i = 0; i < 4; i++) Ac[i] = -__expf(fminf(A_log[s0 + i], 5.f));

    float h[4] = {0.f, 0.f, 0.f, 0.f};

    size_t mbase = (size_t)b * LL;
    // prefetch l = 0
    size_t m = mbase;
    float dt_c = g_dt[m * DI + d];
    float xv_c = g_xiconv[m * DI + d];
    float4 Bv_c = *(const float4*)(g_Bc + m * DS + s0);
    float4 Cv_c = *(const float4*)(g_Cc + m * DS + s0);

    for (int l = 0; l < LL; l++) {
        // prefetch next step
        int ln = (l + 1 < LL) ? (l + 1) : l;
        size_t mn = mbase + ln;
        float dt_n = g_dt[mn * DI + d];
        float xv_n = g_xiconv[mn * DI + d];
        float4 Bv_n = *(const float4*)(g_Bc + mn * DS + s0);
        float4 Cv_n = *(const float4*)(g_Cc + mn * DS + s0);

        float dt = dt_c, xv = xv_c;
        float Bv[4] = {Bv_c.x, Bv_c.y, Bv_c.z, Bv_c.w};
        float Cv[4] = {Cv_c.x, Cv_c.y, Cv_c.z, Cv_c.w};

        float y = 0.f;
        #pragma unroll
        for (int i = 0; i < 4; i++) {
            float dA  = __expf(fmaxf(fminf(dt * Ac[i], 0.f), -20.f));
            float dBu = fminf(fmaxf(dt * Bv[i] * xv, -10.f), 10.f);
            h[i] = fminf(fmaxf(h[i] * dA + dBu, -100.f), 100.f);
            y += h[i] * Cv[i];
        }
        y += __shfl_xor_sync(0xffffffffu, y, 1);
        y += __shfl_xor_sync(0xffffffffu, y, 2);
        if (sub == 0) g_y[(mbase + l) * DI + d] = y;

        dt_c = dt_n; xv_c = xv_n; Bv_c = Bv_n; Cv_c = Cv_n;
    }
}

// ============================================================================
// layernorm(y) -> (yn + D*xi) * silu(z) -> g_outpre      (one block per row)
// ============================================================================
__device__ __forceinline__ float block_reduce_sum(float v) {
    __shared__ float sh[8];
    __syncthreads();
    int lane = threadIdx.x & 31, w = threadIdx.x >> 5;
    #pragma unroll
    for (int o = 16; o; o >>= 1) v += __shfl_xor_sync(0xffffffffu, v, o);
    if (lane == 0) sh[w] = v;
    __syncthreads();
    if (threadIdx.x < 32) {
        v = (threadIdx.x < 8) ? sh[threadIdx.x] : 0.f;
        #pragma unroll
        for (int o = 4; o; o >>= 1) v += __shfl_xor_sync(0xffffffffu, v, o);
        if (threadIdx.x == 0) sh[0] = v;
    }
    __syncthreads();
    return sh[0];
}

__global__ void __launch_bounds__(256) lncomb_kernel(const float* __restrict__ ln_w,
                                                     const float* __restrict__ ln_b,
                                                     const float* __restrict__ D_param) {
    const int m = blockIdx.x;
    const float* yrow = g_y + (size_t)m * DI;

    float s = 0.f;
    for (int dd = threadIdx.x; dd < DI; dd += 256) s += yrow[dd];
    float mu = block_reduce_sum(s) * (1.f / DI);

    float v = 0.f;
    for (int dd = threadIdx.x; dd < DI; dd += 256) {
        float t = yrow[dd] - mu;
        v += t * t;
    }
    float var = block_reduce_sum(v) * (1.f / DI);
    float rstd = rsqrtf(var + 1e-5f);

    for (int dd = threadIdx.x; dd < DI; dd += 256) {
        float yn = (yrow[dd] - mu) * rstd * ln_w[dd] + ln_b[dd];
        float xi = g_xiconv[(size_t)m * DI + dd];
        float z  = g_xz[(size_t)m * NXZ + DI + dd];
        float sz = z / (1.f + expf(-z));
        g_outpre[(size_t)m * DI + dd] = (yn + D_param[dd] * xi) * sz;
    }
}

// ============================================================================
// launch
// ============================================================================
extern "C" void kernel_launch(void* const* d_in, const int* in_sizes, int n_in,
                              void* d_out, int out_size) {
    (void)in_sizes; (void)n_in; (void)out_size;
    const float* x       = (const float*)d_in[0];
    const float* W_in    = (const float*)d_in[1];
    const float* conv_w  = (const float*)d_in[2];
    const float* conv_b  = (const float*)d_in[3];
    const float* W_x     = (const float*)d_in[4];
    const float* W_dt    = (const float*)d_in[5];
    const float* b_dt    = (const float*)d_in[6];
    const float* A_log   = (const float*)d_in[7];
    const float* D_param = (const float*)d_in[8];
    const float* W_out   = (const float*)d_in[9];
    const float* ln_w    = (const float*)d_in[10];
    const float* ln_b    = (const float*)d_in[11];
    float* out = (float*)d_out;

    // 1) xz = x @ W_in^T
    {
        dim3 grid(NXZ / 128, MR / 128);
        gemm_xz_kernel<<<grid, 256>>>(x, W_in);
    }
    // 2) conv + silu
    conv_silu_kernel<<<(MR * DI) / 256, 256>>>(conv_w, conv_b);
    // 3) xd projection (dtraw, B, C)
    projx_kernel<<<MR / 4, 256>>>(W_x);
    // 4) dt expansion
    dt_kernel<<<(MR * DI) / 256, 256>>>(W_dt, b_dt);
    // 5) sequential selective scan
    {
        dim3 grid(DI / 32, BB);
        scan_kernel<<<grid, 128>>>(A_log);
    }
    // 6) layernorm + combine
    lncomb_kernel<<<MR, 256>>>(ln_w, ln_b, D_param);
    // 7) out = outpre @ W_out^T
    {
        dim3 grid(DM / 128, MR / 128);
        gemm_out_kernel<<<grid, 256>>>(W_out, out);
    }
}

// round 4
// speedup vs baseline: 2.0507x; 2.0507x over previous
#include <cuda_runtime.h>
#include <cuda_bf16.h>
#include <cstdint>

// ---------------- problem constants ----------------
constexpr int BB = 4;
constexpr int LL = 2048;
constexpr int DM = 1024;
constexpr int DI = 2048;      // d_inner
constexpr int DS = 16;        // d_state
constexpr int MR = BB * LL;   // 8192 rows
constexpr int NXZ = 2 * DI;   // 4096

// ---------------- scratch (device globals; no allocation allowed) ----------------
__device__ float g_xz[(size_t)MR * NXZ];       // [xi | z]
__device__ float g_xiconv[(size_t)MR * DI];    // silu(conv(xi))
__device__ float g_dtraw[MR];
__device__ float g_Bc[MR * DS];
__device__ float g_Cc[MR * DS];
__device__ float g_dt[(size_t)MR * DI];
__device__ float g_y[(size_t)MR * DI];

// bf16 hi/lo split operands for the tensor-core GEMMs
__device__ __nv_bfloat16 g_xh [(size_t)MR * DM];
__device__ __nv_bfloat16 g_xl [(size_t)MR * DM];
__device__ __nv_bfloat16 g_wih[(size_t)NXZ * DM];
__device__ __nv_bfloat16 g_wil[(size_t)NXZ * DM];
__device__ __nv_bfloat16 g_oph[(size_t)MR * DI];
__device__ __nv_bfloat16 g_opl[(size_t)MR * DI];
__device__ __nv_bfloat16 g_woh[(size_t)DM * DI];
__device__ __nv_bfloat16 g_wol[(size_t)DM * DI];

// ============================================================================
// PTX helpers (portable sm_80+ subset only — NO tcgen05 on this build target)
// ============================================================================
__device__ __forceinline__ uint32_t smem_u32(const void* p) {
    uint32_t a;
    asm("{ .reg .u64 t; cvta.to.shared.u64 t, %1; cvt.u32.u64 %0, t; }" : "=r"(a) : "l"(p));
    return a;
}
__device__ __forceinline__ void cp_async16(uint32_t dst, const void* src) {
    asm volatile("cp.async.cg.shared.global [%0], [%1], 16;" :: "r"(dst), "l"(src));
}
__device__ __forceinline__ void cp_commit() { asm volatile("cp.async.commit_group;"); }
template<int N> __device__ __forceinline__ void cp_wait() {
    asm volatile("cp.async.wait_group %0;" :: "n"(N));
}
__device__ __forceinline__ void ldmx4(uint32_t& r0, uint32_t& r1, uint32_t& r2, uint32_t& r3,
                                      uint32_t addr) {
    asm volatile("ldmatrix.sync.aligned.m8n8.x4.shared.b16 {%0,%1,%2,%3}, [%4];"
                 : "=r"(r0), "=r"(r1), "=r"(r2), "=r"(r3) : "r"(addr));
}
__device__ __forceinline__ void mma_bf16(float* c, const uint32_t* a, const uint32_t* b) {
    asm volatile(
        "mma.sync.aligned.m16n8k16.row.col.f32.bf16.bf16.f32 "
        "{%0,%1,%2,%3}, {%4,%5,%6,%7}, {%8,%9}, {%0,%1,%2,%3};"
        : "+f"(c[0]), "+f"(c[1]), "+f"(c[2]), "+f"(c[3])
        : "r"(a[0]), "r"(a[1]), "r"(a[2]), "r"(a[3]), "r"(b[0]), "r"(b[1]));
}

// ============================================================================
// bf16-split mma.sync GEMM:  C[M,N] = (Ah+Al)[M,K] * (Bh+Bl)[N,K]^T  (fp32 C)
// Block 128x128, BK=32, 8 warps (2x4), warp tile 64x32, double buffer.
// SMEM rows padded to 80B -> conflict-free ldmatrix (bank stride 20 mod 32).
// ============================================================================
constexpr int ROWB   = 80;                  // padded row bytes (32 bf16 data + 16B pad)
constexpr int TILEB  = 128 * ROWB;          // 10240 per operand tile
constexpr int STAGEB = 4 * TILEB;           // Ah, Al, Bh, Bl = 40960
constexpr int GEMM_SMEM = 2 * STAGEB;       // 81920

template<int Ktot>
__device__ __forceinline__ void load_stage(uint32_t stage, int k0, int bm0, int bn0,
                                           const __nv_bfloat16* __restrict__ Ah,
                                           const __nv_bfloat16* __restrict__ Al,
                                           const __nv_bfloat16* __restrict__ Bh,
                                           const __nv_bfloat16* __restrict__ Bl,
                                           int tid) {
    const __nv_bfloat16* srcs[4] = {Ah, Al, Bh, Bl};
    const int row0s[2] = {bm0, bn0};
    #pragma unroll
    for (int i = 0; i < 8; i++) {
        int u = tid + i * 256;          // [0, 2048)
        int s = u >> 9;                 // operand section
        int v = u & 511;
        int r = v >> 2, c = v & 3;
        cp_async16(stage + s * TILEB + r * ROWB + c * 16,
                   srcs[s] + (size_t)(row0s[s >> 1] + r) * Ktot + k0 + c * 8);
    }
    cp_commit();
}

template<int Ntot, int Ktot>
__global__ void __launch_bounds__(256) gemm_mma(const __nv_bfloat16* __restrict__ Ah,
                                                const __nv_bfloat16* __restrict__ Al,
                                                const __nv_bfloat16* __restrict__ Bh,
                                                const __nv_bfloat16* __restrict__ Bl,
                                                float* __restrict__ C) {
    extern __shared__ char smem[];
    const uint32_t sb = smem_u32(smem);
    const int tid  = threadIdx.x;
    const int wid  = tid >> 5, lane = tid & 31;
    const int wm   = wid >> 2;          // 0..1  (M)
    const int wn   = wid & 3;           // 0..3  (N)
    const int bm0  = blockIdx.y * 128;
    const int bn0  = blockIdx.x * 128;
    constexpr int NCHUNK = Ktot / 32;

    float acc[4][4][4];
    #pragma unroll
    for (int i = 0; i < 4; i++)
        #pragma unroll
        for (int j = 0; j < 4; j++)
            #pragma unroll
            for (int q = 0; q < 4; q++) acc[i][j][q] = 0.f;

    // ldmatrix per-lane address components
    const int lrow  = lane & 15;
    const int khalf = (lane >> 4) * 16;  // byte offset of k-half within 16-wide tile

    load_stage<Ktot>(sb, 0, bm0, bn0, Ah, Al, Bh, Bl, tid);

    for (int k = 0; k < NCHUNK; k++) {
        if (k + 1 < NCHUNK) {
            load_stage<Ktot>(sb + ((k + 1) & 1) * STAGEB, (k + 1) * 32, bm0, bn0,
                             Ah, Al, Bh, Bl, tid);
            cp_wait<1>();
        } else {
            cp_wait<0>();
        }
        __syncthreads();

        const uint32_t st = sb + (k & 1) * STAGEB;
        #pragma unroll
        for (int kk = 0; kk < 32; kk += 16) {
            const uint32_t kbyte = kk * 2 + khalf;
            // A fragments (hi + lo): 4 m-tiles
            uint32_t ah[4][4], al[4][4];
            #pragma unroll
            for (int mi = 0; mi < 4; mi++) {
                uint32_t a = st + (wm * 64 + mi * 16 + lrow) * ROWB + kbyte;
                ldmx4(ah[mi][0], ah[mi][1], ah[mi][2], ah[mi][3], a);
                ldmx4(al[mi][0], al[mi][1], al[mi][2], al[mi][3], a + TILEB);
            }
            // B fragments (hi + lo): 2 x ldmatrix.x4 covers 32 n-rows
            uint32_t bh[8], bl[8];
            #pragma unroll
            for (int nj = 0; nj < 2; nj++) {
                uint32_t a = st + 2 * TILEB + (wn * 32 + nj * 16 + lrow) * ROWB + kbyte;
                ldmx4(bh[nj * 4 + 0], bh[nj * 4 + 1], bh[nj * 4 + 2], bh[nj * 4 + 3], a);
                ldmx4(bl[nj * 4 + 0], bl[nj * 4 + 1], bl[nj * 4 + 2], bl[nj * 4 + 3], a + TILEB);
            }
            #pragma unroll
            for (int mi = 0; mi < 4; mi++) {
                #pragma unroll
                for (int ni = 0; ni < 4; ni++) {
                    // n-tile ni: ldmatrix group nj = ni>>1, sub = ni&1
                    const int g = (ni >> 1) * 4 + (ni & 1);
                    uint32_t bhp[2] = {bh[g], bh[g + 2]};
                    uint32_t blp[2] = {bl[g], bl[g + 2]};
                    mma_bf16(acc[mi][ni], ah[mi], bhp);
                    mma_bf16(acc[mi][ni], ah[mi], blp);
                    mma_bf16(acc[mi][ni], al[mi], bhp);
                }
            }
        }
        __syncthreads();
    }

    // epilogue: fp32 direct to global
    #pragma unroll
    for (int mi = 0; mi < 4; mi++) {
        const int r0 = bm0 + wm * 64 + mi * 16 + (lane >> 2);
        #pragma unroll
        for (int ni = 0; ni < 4; ni++) {
            const int c = bn0 + wn * 32 + ni * 8 + (lane & 3) * 2;
            *(float2*)(C + (size_t)r0 * Ntot + c) =
                make_float2(acc[mi][ni][0], acc[mi][ni][1]);
            *(float2*)(C + (size_t)(r0 + 8) * Ntot + c) =
                make_float2(acc[mi][ni][2], acc[mi][ni][3]);
        }
    }
}

// ============================================================================
// fp32 -> bf16 hi/lo split (4 elements / thread)
// ============================================================================
__global__ void __launch_bounds__(256) split_kernel(const float* __restrict__ in,
                                                    __nv_bfloat16* __restrict__ hi,
                                                    __nv_bfloat16* __restrict__ lo,
                                                    int n4) {
    int i = blockIdx.x * 256 + threadIdx.x;
    if (i >= n4) return;
    float4 v = *(const float4*)(in + (size_t)i * 4);
    float vv[4] = {v.x, v.y, v.z, v.w};
    __nv_bfloat16 h[4], l[4];
    #pragma unroll
    for (int q = 0; q < 4; q++) {
        h[q] = __float2bfloat16(vv[q]);
        l[q] = __float2bfloat16(vv[q] - __bfloat162float(h[q]));
    }
    *(uint2*)(hi + (size_t)i * 4) = *(uint2*)h;
    *(uint2*)(lo + (size_t)i * 4) = *(uint2*)l;
}

// ============================================================================
// causal depthwise conv (k=4, pad left 3) + bias + silu
// ============================================================================
__global__ void __launch_bounds__(256) conv_silu_kernel(const float* __restrict__ conv_w,
                                                        const float* __restrict__ conv_b) {
    int idx = blockIdx.x * 256 + threadIdx.x;
    if (idx >= MR * DI) return;
    int c = idx & (DI - 1);
    int m = idx >> 11;
    int l = m & (LL - 1);

    float4 w4 = *(const float4*)(conv_w + c * 4);
    float w[4] = {w4.x, w4.y, w4.z, w4.w};
    const float* base = g_xz + (size_t)m * NXZ + c;
    float s = conv_b[c];
    #pragma unroll
    for (int t = 0; t < 4; t++) {
        int ll = l - 3 + t;
        if (ll >= 0) s += base[(ptrdiff_t)(t - 3) * NXZ] * w[t];
    }
    float sv = s * (1.f / (1.f + __expf(-s)));
    g_xiconv[idx] = sv;
}

// ============================================================================
// xd = xi_conv @ W_x^T  (N=33)
// ============================================================================
__global__ void __launch_bounds__(256) projx_kernel(const float* __restrict__ W_x) {
    __shared__ float xs[4][DI];
    const int m0 = blockIdx.x * 4;
    for (int i = threadIdx.x; i < 4 * DI; i += 256) {
        int r = i >> 11, c = i & (DI - 1);
        xs[r][c] = g_xiconv[(size_t)(m0 + r) * DI + c];
    }
    __syncthreads();

    const int warp = threadIdx.x >> 5;
    const int lane = threadIdx.x & 31;
    for (int n = warp; n < 2 * DS + 1; n += 8) {
        const float* w = W_x + n * DI;
        float a0 = 0.f, a1 = 0.f, a2 = 0.f, a3 = 0.f;
        for (int k = lane * 4; k < DI; k += 128) {
            float4 wv = *(const float4*)(w + k);
            float4 x0 = *(const float4*)&xs[0][k];
            float4 x1 = *(const float4*)&xs[1][k];
            float4 x2 = *(const float4*)&xs[2][k];
            float4 x3 = *(const float4*)&xs[3][k];
            a0 += wv.x * x0.x + wv.y * x0.y + wv.z * x0.z + wv.w * x0.w;
            a1 += wv.x * x1.x + wv.y * x1.y + wv.z * x1.z + wv.w * x1.w;
            a2 += wv.x * x2.x + wv.y * x2.y + wv.z * x2.z + wv.w * x2.w;
            a3 += wv.x * x3.x + wv.y * x3.y + wv.z * x3.z + wv.w * x3.w;
        }
        #pragma unroll
        for (int off = 16; off; off >>= 1) {
            a0 += __shfl_xor_sync(0xffffffffu, a0, off);
            a1 += __shfl_xor_sync(0xffffffffu, a1, off);
            a2 += __shfl_xor_sync(0xffffffffu, a2, off);
            a3 += __shfl_xor_sync(0xffffffffu, a3, off);
        }
        if (lane == 0) {
            float acc[4] = {a0, a1, a2, a3};
            #pragma unroll
            for (int r = 0; r < 4; r++) {
                int m = m0 + r;
                if (n == 0)            g_dtraw[m] = acc[r];
                else if (n < 1 + DS)   g_Bc[m * DS + (n - 1)] = acc[r];
                else                   g_Cc[m * DS + (n - 1 - DS)] = acc[r];
            }
        }
    }
}

// ============================================================================
// dt = clip(softplus(dtraw * W_dt[d] + b_dt[d]), 1e-4, 10)
// ============================================================================
__global__ void __launch_bounds__(256) dt_kernel(const float* __restrict__ W_dt,
                                                 const float* __restrict__ b_dt) {
    int idx = blockIdx.x * 256 + threadIdx.x;
    if (idx >= MR * DI) return;
    int d = idx & (DI - 1);
    int m = idx >> 11;
    float xx = g_dtraw[m] * W_dt[d] + b_dt[d];
    float sp = fmaxf(xx, 0.f) + __logf(1.f + __expf(-fabsf(xx)));
    g_dt[idx] = fminf(fmaxf(sp, 1e-4f), 10.f);
}

// ============================================================================
// selective scan: 4 threads per (b,d) channel, 4 states each, 8-deep prefetch
// ============================================================================
__global__ void __launch_bounds__(128) scan_kernel(const float* __restrict__ A_log) {
    const int sub  = threadIdx.x & 3;
    const int dloc = threadIdx.x >> 2;
    const int d    = blockIdx.x * 32 + dloc;
    const int b    = blockIdx.y;
    const int s0   = sub * 4;

    float Ac[4];
    #pragma unroll
    for (int i = 0; i < 4; i++) Ac[i] = -__expf(fminf(A_log[s0 + i], 5.f));

    float h[4] = {0.f, 0.f, 0.f, 0.f};

    const size_t mbase = (size_t)b * LL;
    constexpr int PF = 8;
    float  dt_b[PF], xv_b[PF];
    float4 Bv_b[PF], Cv_b[PF];
    #pragma unroll
    for (int u = 0; u < PF; u++) {
        size_t m = mbase + u;
        dt_b[u] = g_dt[m * DI + d];
        xv_b[u] = g_xiconv[m * DI + d];
        Bv_b[u] = *(const float4*)(g_Bc + m * DS + s0);
        Cv_b[u] = *(const float4*)(g_Cc + m * DS + s0);
    }

    for (int l0 = 0; l0 < LL; l0 += PF) {
        #pragma unroll
        for (int u = 0; u < PF; u++) {
            const int l = l0 + u;
            const float  dt = dt_b[u], xv = xv_b[u];
            const float4 Bq = Bv_b[u], Cq = Cv_b[u];

            const int lp = l + PF;
            if (lp < LL) {
                size_t mp = mbase + lp;
                dt_b[u] = g_dt[mp * DI + d];
                xv_b[u] = g_xiconv[mp * DI + d];
                Bv_b[u] = *(const float4*)(g_Bc + mp * DS + s0);
                Cv_b[u] = *(const float4*)(g_Cc + mp * DS + s0);
            }

            float Bv[4] = {Bq.x, Bq.y, Bq.z, Bq.w};
            float Cv[4] = {Cq.x, Cq.y, Cq.z, Cq.w};
            float y = 0.f;
            #pragma unroll
            for (int i = 0; i < 4; i++) {
                float dA  = __expf(fmaxf(fminf(dt * Ac[i], 0.f), -20.f));
                float dBu = fminf(fmaxf(dt * Bv[i] * xv, -10.f), 10.f);
                h[i] = fminf(fmaxf(h[i] * dA + dBu, -100.f), 100.f);
                y += h[i] * Cv[i];
            }
            y += __shfl_xor_sync(0xffffffffu, y, 1);
            y += __shfl_xor_sync(0xffffffffu, y, 2);
            if (sub == 0) g_y[(mbase + l) * DI + d] = y;
        }
    }
}

// ============================================================================
// layernorm(y) -> (yn + D*xi) * silu(z) -> bf16 hi/lo (g_oph/g_opl)
// ============================================================================
__device__ __forceinline__ float block_reduce_sum(float v) {
    __shared__ float sh[8];
    __syncthreads();
    int lane = threadIdx.x & 31, w = threadIdx.x >> 5;
    #pragma unroll
    for (int o = 16; o; o >>= 1) v += __shfl_xor_sync(0xffffffffu, v, o);
    if (lane == 0) sh[w] = v;
    __syncthreads();
    if (threadIdx.x < 32) {
        v = (threadIdx.x < 8) ? sh[threadIdx.x] : 0.f;
        #pragma unroll
        for (int o = 4; o; o >>= 1) v += __shfl_xor_sync(0xffffffffu, v, o);
        if (threadIdx.x == 0) sh[0] = v;
    }
    __syncthreads();
    return sh[0];
}

__global__ void __launch_bounds__(256) lncomb_kernel(const float* __restrict__ ln_w,
                                                     const float* __restrict__ ln_b,
                                                     const float* __restrict__ D_param) {
    const int m = blockIdx.x;
    const float* yrow = g_y + (size_t)m * DI;

    float s = 0.f;
    for (int dd = threadIdx.x; dd < DI; dd += 256) s += yrow[dd];
    float mu = block_reduce_sum(s) * (1.f / DI);

    float v = 0.f;
    for (int dd = threadIdx.x; dd < DI; dd += 256) {
        float t = yrow[dd] - mu;
        v += t * t;
    }
    float var = block_reduce_sum(v) * (1.f / DI);
    float rstd = rsqrtf(var + 1e-5f);

    for (int dd = threadIdx.x; dd < DI; dd += 256) {
        float yn = (yrow[dd] - mu) * rstd * ln_w[dd] + ln_b[dd];
        float xi = g_xiconv[(size_t)m * DI + dd];
        float z  = g_xz[(size_t)m * NXZ + DI + dd];
        float sz = z * (1.f / (1.f + __expf(-z)));
        float val = (yn + D_param[dd] * xi) * sz;
        __nv_bfloat16 hh = __float2bfloat16(val);
        g_oph[(size_t)m * DI + dd] = hh;
        g_opl[(size_t)m * DI + dd] = __float2bfloat16(val - __bfloat162float(hh));
    }
}

// ============================================================================
// launch
// ============================================================================
extern "C" void kernel_launch(void* const* d_in, const int* in_sizes, int n_in,
                              void* d_out, int out_size) {
    (void)in_sizes; (void)n_in; (void)out_size;
    const float* x       = (const float*)d_in[0];
    const float* W_in    = (const float*)d_in[1];
    const float* conv_w  = (const float*)d_in[2];
    const float* conv_b  = (const float*)d_in[3];
    const float* W_x     = (const float*)d_in[4];
    const float* W_dt    = (const float*)d_in[5];
    const float* b_dt    = (const float*)d_in[6];
    const float* A_log   = (const float*)d_in[7];
    const float* D_param = (const float*)d_in[8];
    const float* W_out   = (const float*)d_in[9];
    const float* ln_w    = (const float*)d_in[10];
    const float* ln_b    = (const float*)d_in[11];
    float* out = (float*)d_out;

    static __nv_bfloat16 *p_xh = nullptr, *p_xl, *p_wih, *p_wil, *p_oph, *p_opl, *p_woh, *p_wol;
    static float *p_xz = nullptr;
    if (!p_xh) {
        cudaGetSymbolAddress((void**)&p_xh,  g_xh);
        cudaGetSymbolAddress((void**)&p_xl,  g_xl);
        cudaGetSymbolAddress((void**)&p_wih, g_wih);
        cudaGetSymbolAddress((void**)&p_wil, g_wil);
        cudaGetSymbolAddress((void**)&p_oph, g_oph);
        cudaGetSymbolAddress((void**)&p_opl, g_opl);
        cudaGetSymbolAddress((void**)&p_woh, g_woh);
        cudaGetSymbolAddress((void**)&p_wol, g_wol);
        cudaGetSymbolAddress((void**)&p_xz,  g_xz);
        cudaFuncSetAttribute(gemm_mma<NXZ, DM>,
                             cudaFuncAttributeMaxDynamicSharedMemorySize, GEMM_SMEM);
        cudaFuncSetAttribute(gemm_mma<DM, DI>,
                             cudaFuncAttributeMaxDynamicSharedMemorySize, GEMM_SMEM);
    }

    // 0) fp32 -> bf16 hi/lo splits
    split_kernel<<<(MR * DM / 4 + 255) / 256, 256>>>(x, p_xh, p_xl, MR * DM / 4);
    split_kernel<<<(NXZ * DM / 4 + 255) / 256, 256>>>(W_in, p_wih, p_wil, NXZ * DM / 4);
    split_kernel<<<(DM * DI / 4 + 255) / 256, 256>>>(W_out, p_woh, p_wol, DM * DI / 4);

    // 1) xz = x @ W_in^T   (mma.sync, bf16-split)
    {
        dim3 grid(NXZ / 128, MR / 128);
        gemm_mma<NXZ, DM><<<grid, 256, GEMM_SMEM>>>(p_xh, p_xl, p_wih, p_wil, p_xz);
    }
    // 2) conv + silu
    conv_silu_kernel<<<(MR * DI) / 256, 256>>>(conv_w, conv_b);
    // 3) xd projection (dtraw, B, C)
    projx_kernel<<<MR / 4, 256>>>(W_x);
    // 4) dt expansion
    dt_kernel<<<(MR * DI) / 256, 256>>>(W_dt, b_dt);
    // 5) sequential selective scan
    {
        dim3 grid(DI / 32, BB);
        scan_kernel<<<grid, 128>>>(A_log);
    }
    // 6) layernorm + combine (writes bf16 hi/lo outpre)
    lncomb_kernel<<<MR, 256>>>(ln_w, ln_b, D_param);
    // 7) out = outpre @ W_out^T   (mma.sync, bf16-split)
    {
        dim3 grid(DM / 128, MR / 128);
        gemm_mma<DM, DI><<<grid, 256, GEMM_SMEM>>>(p_oph, p_opl, p_woh, p_wol, out);
    }
}

// round 5
// speedup vs baseline: 2.2221x; 1.0836x over previous
#include <cuda_runtime.h>
#include <cuda_bf16.h>
#include <cstdint>

// ---------------- problem constants ----------------
constexpr int BB = 4;
constexpr int LL = 2048;
constexpr int DM = 1024;
constexpr int DI = 2048;      // d_inner
constexpr int DS = 16;        // d_state
constexpr int MR = BB * LL;   // 8192 rows
constexpr int NXZ = 2 * DI;   // 4096

// ---------------- scratch (device globals; no allocation allowed) ----------------
__device__ float g_xz[(size_t)MR * NXZ];       // [xi | z]
__device__ float g_xiconv[(size_t)MR * DI];    // silu(conv(xi))
__device__ float g_dtraw[MR];
__device__ float g_Bc[MR * DS];
__device__ float g_Cc[MR * DS];
__device__ float g_y[(size_t)MR * DI];

// bf16 hi/lo split operands for the tensor-core GEMMs
__device__ __nv_bfloat16 g_xh [(size_t)MR * DM];
__device__ __nv_bfloat16 g_xl [(size_t)MR * DM];
__device__ __nv_bfloat16 g_wih[(size_t)NXZ * DM];
__device__ __nv_bfloat16 g_wil[(size_t)NXZ * DM];
__device__ __nv_bfloat16 g_oph[(size_t)MR * DI];
__device__ __nv_bfloat16 g_opl[(size_t)MR * DI];
__device__ __nv_bfloat16 g_woh[(size_t)DM * DI];
__device__ __nv_bfloat16 g_wol[(size_t)DM * DI];

// ============================================================================
// PTX helpers (portable sm_80+ subset only — NO tcgen05 on this build target)
// ============================================================================
__device__ __forceinline__ uint32_t smem_u32(const void* p) {
    uint32_t a;
    asm("{ .reg .u64 t; cvta.to.shared.u64 t, %1; cvt.u32.u64 %0, t; }" : "=r"(a) : "l"(p));
    return a;
}
__device__ __forceinline__ void cp_async16(uint32_t dst, const void* src) {
    asm volatile("cp.async.cg.shared.global [%0], [%1], 16;" :: "r"(dst), "l"(src));
}
__device__ __forceinline__ void cp_commit() { asm volatile("cp.async.commit_group;"); }
template<int N> __device__ __forceinline__ void cp_wait() {
    asm volatile("cp.async.wait_group %0;" :: "n"(N));
}
__device__ __forceinline__ void ldmx4(uint32_t& r0, uint32_t& r1, uint32_t& r2, uint32_t& r3,
                                      uint32_t addr) {
    asm volatile("ldmatrix.sync.aligned.m8n8.x4.shared.b16 {%0,%1,%2,%3}, [%4];"
                 : "=r"(r0), "=r"(r1), "=r"(r2), "=r"(r3) : "r"(addr));
}
__device__ __forceinline__ void mma_bf16(float* c, const uint32_t* a, const uint32_t* b) {
    asm volatile(
        "mma.sync.aligned.m16n8k16.row.col.f32.bf16.bf16.f32 "
        "{%0,%1,%2,%3}, {%4,%5,%6,%7}, {%8,%9}, {%0,%1,%2,%3};"
        : "+f"(c[0]), "+f"(c[1]), "+f"(c[2]), "+f"(c[3])
        : "r"(a[0]), "r"(a[1]), "r"(a[2]), "r"(a[3]), "r"(b[0]), "r"(b[1]));
}
// SW64 swizzle on byte offsets within a (128-row x 64B) tile. 16B-granular.
__device__ __forceinline__ uint32_t swz64(uint32_t off) {
    return off ^ ((off >> 3) & 0x30);
}

// ============================================================================
// bf16-split mma.sync GEMM:  C[M,N] = (Ah+Al)[M,K] * (Bh+Bl)[N,K]^T  (fp32 C)
// Block 128x128, BK=32, 8 warps (2x4), warp tile 64x32.
// SW64-swizzled 64B rows; 3-stage cp.async pipeline.
// ============================================================================
constexpr int ROWB   = 64;                  // row bytes (32 bf16, no pad - swizzled)
constexpr int TILEB  = 128 * ROWB;          // 8192 per operand tile
constexpr int STAGEB = 4 * TILEB;           // Ah, Al, Bh, Bl = 32768
constexpr int NSTAGE = 3;
constexpr int GEMM_SMEM = NSTAGE * STAGEB;  // 98304

template<int Ktot>
__device__ __forceinline__ void load_stage(uint32_t stage, int k0, int bm0, int bn0,
                                           const __nv_bfloat16* __restrict__ Ah,
                                           const __nv_bfloat16* __restrict__ Al,
                                           const __nv_bfloat16* __restrict__ Bh,
                                           const __nv_bfloat16* __restrict__ Bl,
                                           int tid) {
    const __nv_bfloat16* srcs[4] = {Ah, Al, Bh, Bl};
    const int row0s[2] = {bm0, bn0};
    #pragma unroll
    for (int i = 0; i < 8; i++) {
        int u = tid + i * 256;          // [0, 2048)
        int s = u >> 9;                 // operand section
        int v = u & 511;
        int r = v >> 2, c = v & 3;
        cp_async16(stage + s * TILEB + swz64(r * ROWB + c * 16),
                   srcs[s] + (size_t)(row0s[s >> 1] + r) * Ktot + k0 + c * 8);
    }
    cp_commit();
}

template<int Ntot, int Ktot>
__global__ void __launch_bounds__(256) gemm_mma(const __nv_bfloat16* __restrict__ Ah,
                                                const __nv_bfloat16* __restrict__ Al,
                                                const __nv_bfloat16* __restrict__ Bh,
                                                const __nv_bfloat16* __restrict__ Bl,
                                                float* __restrict__ C) {
    extern __shared__ char smem[];
    const uint32_t sb = smem_u32(smem);
    const int tid  = threadIdx.x;
    const int wid  = tid >> 5, lane = tid & 31;
    const int wm   = wid >> 2;          // 0..1  (M)
    const int wn   = wid & 3;           // 0..3  (N)
    const int bm0  = blockIdx.y * 128;
    const int bn0  = blockIdx.x * 128;
    constexpr int NCHUNK = Ktot / 32;

    float acc[4][4][4];
    #pragma unroll
    for (int i = 0; i < 4; i++)
        #pragma unroll
        for (int j = 0; j < 4; j++)
            #pragma unroll
            for (int q = 0; q < 4; q++) acc[i][j][q] = 0.f;

    // ldmatrix per-lane address components
    const int lrow  = lane & 15;
    const int khalf = (lane >> 4) * 16;   // 16B half select within a 32B k-slab
    const uint32_t aRow = (wm * 64 + lrow) * ROWB;
    const uint32_t bRow = (wn * 32 + lrow) * ROWB;

    load_stage<Ktot>(sb, 0, bm0, bn0, Ah, Al, Bh, Bl, tid);
    load_stage<Ktot>(sb + STAGEB, 32, bm0, bn0, Ah, Al, Bh, Bl, tid);

    uint32_t stOff = 0;                 // compute buffer offset
    uint32_t ldOff = 2 * STAGEB;        // next load buffer offset

    for (int k = 0; k < NCHUNK; k++) {
        if (k + 2 < NCHUNK) {
            load_stage<Ktot>(sb + ldOff, (k + 2) * 32, bm0, bn0, Ah, Al, Bh, Bl, tid);
            ldOff += STAGEB; if (ldOff == NSTAGE * STAGEB) ldOff = 0;
            cp_wait<2>();
        } else if (k + 1 < NCHUNK) {
            cp_wait<1>();
        } else {
            cp_wait<0>();
        }
        __syncthreads();

        const uint32_t st = sb + stOff;
        #pragma unroll
        for (int kk = 0; kk < 32; kk += 16) {
            const uint32_t kbyte = kk * 2 + khalf;
            // A fragments (hi + lo): 4 m-tiles
            uint32_t ah[4][4], al[4][4];
            #pragma unroll
            for (int mi = 0; mi < 4; mi++) {
                uint32_t a = st + swz64(aRow + mi * 16 * ROWB + kbyte);
                ldmx4(ah[mi][0], ah[mi][1], ah[mi][2], ah[mi][3], a);
                ldmx4(al[mi][0], al[mi][1], al[mi][2], al[mi][3], a + TILEB);
            }
            // B fragments (hi + lo): 2 x ldmatrix.x4 covers 32 n-rows
            uint32_t bh[8], bl[8];
            #pragma unroll
            for (int nj = 0; nj < 2; nj++) {
                uint32_t a = st + 2 * TILEB + swz64(bRow + nj * 16 * ROWB + kbyte);
                ldmx4(bh[nj * 4 + 0], bh[nj * 4 + 1], bh[nj * 4 + 2], bh[nj * 4 + 3], a);
                ldmx4(bl[nj * 4 + 0], bl[nj * 4 + 1], bl[nj * 4 + 2], bl[nj * 4 + 3], a + TILEB);
            }
            #pragma unroll
            for (int mi = 0; mi < 4; mi++) {
                #pragma unroll
                for (int ni = 0; ni < 4; ni++) {
                    const int g = (ni >> 1) * 4 + (ni & 1);
                    uint32_t bhp[2] = {bh[g], bh[g + 2]};
                    uint32_t blp[2] = {bl[g], bl[g + 2]};
                    mma_bf16(acc[mi][ni], ah[mi], bhp);
                    mma_bf16(acc[mi][ni], ah[mi], blp);
                    mma_bf16(acc[mi][ni], al[mi], bhp);
                }
            }
        }
        __syncthreads();
        stOff += STAGEB; if (stOff == NSTAGE * STAGEB) stOff = 0;
    }

    // epilogue: fp32 direct to global
    #pragma unroll
    for (int mi = 0; mi < 4; mi++) {
        const int r0 = bm0 + wm * 64 + mi * 16 + (lane >> 2);
        #pragma unroll
        for (int ni = 0; ni < 4; ni++) {
            const int c = bn0 + wn * 32 + ni * 8 + (lane & 3) * 2;
            *(float2*)(C + (size_t)r0 * Ntot + c) =
                make_float2(acc[mi][ni][0], acc[mi][ni][1]);
            *(float2*)(C + (size_t)(r0 + 8) * Ntot + c) =
                make_float2(acc[mi][ni][2], acc[mi][ni][3]);
        }
    }
}

// ============================================================================
// fp32 -> bf16 hi/lo split (4 elements / thread)
// ============================================================================
__global__ void __launch_bounds__(256) split_kernel(const float* __restrict__ in,
                                                    __nv_bfloat16* __restrict__ hi,
                                                    __nv_bfloat16* __restrict__ lo,
                                                    int n4) {
    int i = blockIdx.x * 256 + threadIdx.x;
    if (i >= n4) return;
    float4 v = *(const float4*)(in + (size_t)i * 4);
    float vv[4] = {v.x, v.y, v.z, v.w};
    __nv_bfloat16 h[4], l[4];
    #pragma unroll
    for (int q = 0; q < 4; q++) {
        h[q] = __float2bfloat16(vv[q]);
        l[q] = __float2bfloat16(vv[q] - __bfloat162float(h[q]));
    }
    *(uint2*)(hi + (size_t)i * 4) = *(uint2*)h;
    *(uint2*)(lo + (size_t)i * 4) = *(uint2*)l;
}

// ============================================================================
// causal depthwise conv (k=4, pad left 3) + bias + silu
// ============================================================================
__global__ void __launch_bounds__(256) conv_silu_kernel(const float* __restrict__ conv_w,
                                                        const float* __restrict__ conv_b) {
    int idx = blockIdx.x * 256 + threadIdx.x;
    if (idx >= MR * DI) return;
    int c = idx & (DI - 1);
    int m = idx >> 11;
    int l = m & (LL - 1);

    float4 w4 = *(const float4*)(conv_w + c * 4);
    float w[4] = {w4.x, w4.y, w4.z, w4.w};
    const float* base = g_xz + (size_t)m * NXZ + c;
    float s = conv_b[c];
    #pragma unroll
    for (int t = 0; t < 4; t++) {
        int ll = l - 3 + t;
        if (ll >= 0) s += base[(ptrdiff_t)(t - 3) * NXZ] * w[t];
    }
    float sv = s * (1.f / (1.f + __expf(-s)));
    g_xiconv[idx] = sv;
}

// ============================================================================
// xd = xi_conv @ W_x^T  (N=33). 4 rows/block; each warp handles 4 n-columns
// simultaneously so smem xs reads are amortized 4x.
// ============================================================================
__global__ void __launch_bounds__(256) projx_kernel(const float* __restrict__ W_x) {
    __shared__ float xs[4][DI];
    const int m0 = blockIdx.x * 4;
    for (int i = threadIdx.x; i < 4 * DI; i += 256) {
        int r = i >> 11, c = i & (DI - 1);
        xs[r][c] = g_xiconv[(size_t)(m0 + r) * DI + c];
    }
    __syncthreads();

    const int warp = threadIdx.x >> 5;
    const int lane = threadIdx.x & 31;
    // 9 groups of 4 n's (last group has only n=32)
    for (int g = warp; g < 9; g += 8) {
        const int nbase = g * 4;
        const int ncnt  = (g == 8) ? 1 : 4;
        float acc[4][4];                // [nn][row]
        #pragma unroll
        for (int a = 0; a < 4; a++)
            #pragma unroll
            for (int r = 0; r < 4; r++) acc[a][r] = 0.f;

        for (int k = lane * 4; k < DI; k += 128) {
            float4 xr[4];
            #pragma unroll
            for (int r = 0; r < 4; r++) xr[r] = *(const float4*)&xs[r][k];
            for (int nn = 0; nn < ncnt; nn++) {
                float4 wv = *(const float4*)(W_x + (size_t)(nbase + nn) * DI + k);
                #pragma unroll
                for (int r = 0; r < 4; r++) {
                    acc[nn][r] += wv.x * xr[r].x + wv.y * xr[r].y
                                + wv.z * xr[r].z + wv.w * xr[r].w;
                }
            }
        }
        for (int nn = 0; nn < ncnt; nn++) {
            #pragma unroll
            for (int r = 0; r < 4; r++) {
                float v = acc[nn][r];
                #pragma unroll
                for (int off = 16; off; off >>= 1)
                    v += __shfl_xor_sync(0xffffffffu, v, off);
                acc[nn][r] = v;
            }
            if (lane == 0) {
                const int n = nbase + nn;
                #pragma unroll
                for (int r = 0; r < 4; r++) {
                    int m = m0 + r;
                    if (n == 0)            g_dtraw[m] = acc[nn][r];
                    else if (n < 1 + DS)   g_Bc[m * DS + (n - 1)] = acc[nn][r];
                    else                   g_Cc[m * DS + (n - 1 - DS)] = acc[nn][r];
                }
            }
        }
    }
}

// ============================================================================
// selective scan with fused dt: 4 threads per (b,d) channel, 4 states each,
// 8-deep prefetch. dt = clip(softplus(dtraw[m]*W_dt[d]+b_dt[d]), 1e-4, 10)
// computed inline (off the h->h dependency chain).
// ============================================================================
__global__ void __launch_bounds__(128) scan_kernel(const float* __restrict__ A_log,
                                                   const float* __restrict__ W_dt,
                                                   const float* __restrict__ b_dt) {
    const int sub  = threadIdx.x & 3;
    const int dloc = threadIdx.x >> 2;
    const int d    = blockIdx.x * 32 + dloc;
    const int b    = blockIdx.y;
    const int s0   = sub * 4;

    float Ac[4];
    #pragma unroll
    for (int i = 0; i < 4; i++) Ac[i] = -__expf(fminf(A_log[s0 + i], 5.f));
    const float Wd = W_dt[d];
    const float bd = b_dt[d];

    float h[4] = {0.f, 0.f, 0.f, 0.f};

    const size_t mbase = (size_t)b * LL;
    constexpr int PF = 8;
    float  dr_b[PF], xv_b[PF];
    float4 Bv_b[PF], Cv_b[PF];
    #pragma unroll
    for (int u = 0; u < PF; u++) {
        size_t m = mbase + u;
        dr_b[u] = g_dtraw[m];
        xv_b[u] = g_xiconv[m * DI + d];
        Bv_b[u] = *(const float4*)(g_Bc + m * DS + s0);
        Cv_b[u] = *(const float4*)(g_Cc + m * DS + s0);
    }

    for (int l0 = 0; l0 < LL; l0 += PF) {
        #pragma unroll
        for (int u = 0; u < PF; u++) {
            const int l = l0 + u;
            const float  dr = dr_b[u], xv = xv_b[u];
            const float4 Bq = Bv_b[u], Cq = Cv_b[u];

            const int lp = l + PF;
            if (lp < LL) {
                size_t mp = mbase + lp;
                dr_b[u] = g_dtraw[mp];
                xv_b[u] = g_xiconv[mp * DI + d];
                Bv_b[u] = *(const float4*)(g_Bc + mp * DS + s0);
                Cv_b[u] = *(const float4*)(g_Cc + mp * DS + s0);
            }

            // fused softplus dt
            float xx = dr * Wd + bd;
            float sp = fmaxf(xx, 0.f) + __logf(1.f + __expf(-fabsf(xx)));
            float dt = fminf(fmaxf(sp, 1e-4f), 10.f);

            float Bv[4] = {Bq.x, Bq.y, Bq.z, Bq.w};
            float Cv[4] = {Cq.x, Cq.y, Cq.z, Cq.w};
            float y = 0.f;
            #pragma unroll
            for (int i = 0; i < 4; i++) {
                float dA  = __expf(fmaxf(fminf(dt * Ac[i], 0.f), -20.f));
                float dBu = fminf(fmaxf(dt * Bv[i] * xv, -10.f), 10.f);
                h[i] = fminf(fmaxf(h[i] * dA + dBu, -100.f), 100.f);
                y += h[i] * Cv[i];
            }
            y += __shfl_xor_sync(0xffffffffu, y, 1);
            y += __shfl_xor_sync(0xffffffffu, y, 2);
            if (sub == 0) g_y[(mbase + l) * DI + d] = y;
        }
    }
}

// ============================================================================
// layernorm(y) -> (yn + D*xi) * silu(z) -> bf16 hi/lo (g_oph/g_opl)
// ============================================================================
__device__ __forceinline__ float block_reduce_sum(float v) {
    __shared__ float sh[8];
    __syncthreads();
    int lane = threadIdx.x & 31, w = threadIdx.x >> 5;
    #pragma unroll
    for (int o = 16; o; o >>= 1) v += __shfl_xor_sync(0xffffffffu, v, o);
    if (lane == 0) sh[w] = v;
    __syncthreads();
    if (threadIdx.x < 32) {
        v = (threadIdx.x < 8) ? sh[threadIdx.x] : 0.f;
        #pragma unroll
        for (int o = 4; o; o >>= 1) v += __shfl_xor_sync(0xffffffffu, v, o);
        if (threadIdx.x == 0) sh[0] = v;
    }
    __syncthreads();
    return sh[0];
}

__global__ void __launch_bounds__(256) lncomb_kernel(const float* __restrict__ ln_w,
                                                     const float* __restrict__ ln_b,
                                                     const float* __restrict__ D_param) {
    const int m = blockIdx.x;
    const float* yrow = g_y + (size_t)m * DI;

    float s = 0.f;
    for (int dd = threadIdx.x; dd < DI; dd += 256) s += yrow[dd];
    float mu = block_reduce_sum(s) * (1.f / DI);

    float v = 0.f;
    for (int dd = threadIdx.x; dd < DI; dd += 256) {
        float t = yrow[dd] - mu;
        v += t * t;
    }
    float var = block_reduce_sum(v) * (1.f / DI);
    float rstd = rsqrtf(var + 1e-5f);

    for (int dd = threadIdx.x; dd < DI; dd += 256) {
        float yn = (yrow[dd] - mu) * rstd * ln_w[dd] + ln_b[dd];
        float xi = g_xiconv[(size_t)m * DI + dd];
        float z  = g_xz[(size_t)m * NXZ + DI + dd];
        float sz = z * (1.f / (1.f + __expf(-z)));
        float val = (yn + D_param[dd] * xi) * sz;
        __nv_bfloat16 hh = __float2bfloat16(val);
        g_oph[(size_t)m * DI + dd] = hh;
        g_opl[(size_t)m * DI + dd] = __float2bfloat16(val - __bfloat162float(hh));
    }
}

// ============================================================================
// launch
// ============================================================================
extern "C" void kernel_launch(void* const* d_in, const int* in_sizes, int n_in,
                              void* d_out, int out_size) {
    (void)in_sizes; (void)n_in; (void)out_size;
    const float* x       = (const float*)d_in[0];
    const float* W_in    = (const float*)d_in[1];
    const float* conv_w  = (const float*)d_in[2];
    const float* conv_b  = (const float*)d_in[3];
    const float* W_x     = (const float*)d_in[4];
    const float* W_dt    = (const float*)d_in[5];
    const float* b_dt    = (const float*)d_in[6];
    const float* A_log   = (const float*)d_in[7];
    const float* D_param = (const float*)d_in[8];
    const float* W_out   = (const float*)d_in[9];
    const float* ln_w    = (const float*)d_in[10];
    const float* ln_b    = (const float*)d_in[11];
    float* out = (float*)d_out;

    static __nv_bfloat16 *p_xh = nullptr, *p_xl, *p_wih, *p_wil, *p_oph, *p_opl, *p_woh, *p_wol;
    static float *p_xz = nullptr;
    if (!p_xh) {
        cudaGetSymbolAddress((void**)&p_xh,  g_xh);
        cudaGetSymbolAddress((void**)&p_xl,  g_xl);
        cudaGetSymbolAddress((void**)&p_wih, g_wih);
        cudaGetSymbolAddress((void**)&p_wil, g_wil);
        cudaGetSymbolAddress((void**)&p_oph, g_oph);
        cudaGetSymbolAddress((void**)&p_opl, g_opl);
        cudaGetSymbolAddress((void**)&p_woh, g_woh);
        cudaGetSymbolAddress((void**)&p_wol, g_wol);
        cudaGetSymbolAddress((void**)&p_xz,  g_xz);
        cudaFuncSetAttribute(gemm_mma<NXZ, DM>,
                             cudaFuncAttributeMaxDynamicSharedMemorySize, GEMM_SMEM);
        cudaFuncSetAttribute(gemm_mma<DM, DI>,
                             cudaFuncAttributeMaxDynamicSharedMemorySize, GEMM_SMEM);
    }

    // 0) fp32 -> bf16 hi/lo splits
    split_kernel<<<(MR * DM / 4 + 255) / 256, 256>>>(x, p_xh, p_xl, MR * DM / 4);
    split_kernel<<<(NXZ * DM / 4 + 255) / 256, 256>>>(W_in, p_wih, p_wil, NXZ * DM / 4);
    split_kernel<<<(DM * DI / 4 + 255) / 256, 256>>>(W_out, p_woh, p_wol, DM * DI / 4);

    // 1) xz = x @ W_in^T   (mma.sync, bf16-split)
    {
        dim3 grid(NXZ / 128, MR / 128);
        gemm_mma<NXZ, DM><<<grid, 256, GEMM_SMEM>>>(p_xh, p_xl, p_wih, p_wil, p_xz);
    }
    // 2) conv + silu
    conv_silu_kernel<<<(MR * DI) / 256, 256>>>(conv_w, conv_b);
    // 3) xd projection (dtraw, B, C)
    projx_kernel<<<MR / 4, 256>>>(W_x);
    // 4) sequential selective scan (dt fused)
    {
        dim3 grid(DI / 32, BB);
        scan_kernel<<<grid, 128>>>(A_log, W_dt, b_dt);
    }
    // 5) layernorm + combine (writes bf16 hi/lo outpre)
    lncomb_kernel<<<MR, 256>>>(ln_w, ln_b, D_param);
    // 6) out = outpre @ W_out^T   (mma.sync, bf16-split)
    {
        dim3 grid(DM / 128, MR / 128);
        gemm_mma<DM, DI><<<grid, 256, GEMM_SMEM>>>(p_oph, p_opl, p_woh, p_wol, out);
    }
}

// round 6
// speedup vs baseline: 2.4788x; 1.1155x over previous
#include <cuda_runtime.h>
#include <cuda_bf16.h>
#include <cstdint>

// ---------------- problem constants ----------------
constexpr int BB = 4;
constexpr int LL = 2048;
constexpr int DM = 1024;
constexpr int DI = 2048;      // d_inner
constexpr int DS = 16;        // d_state
constexpr int MR = BB * LL;   // 8192 rows
constexpr int NXZ = 2 * DI;   // 4096

// ---------------- scratch (device globals; no allocation allowed) ----------------
__device__ float g_xz[(size_t)MR * NXZ];       // [xi | z]
__device__ float g_xiconv[(size_t)MR * DI];    // silu(conv(xi))
__device__ float g_dtraw[MR];
__device__ float g_Bc[MR * DS];
__device__ float g_Cc[MR * DS];
__device__ float g_y[(size_t)MR * DI];

// bf16 hi/lo split operands for the tensor-core GEMMs
__device__ __nv_bfloat16 g_xh [(size_t)MR * DM];
__device__ __nv_bfloat16 g_xl [(size_t)MR * DM];
__device__ __nv_bfloat16 g_wih[(size_t)NXZ * DM];
__device__ __nv_bfloat16 g_wil[(size_t)NXZ * DM];
__device__ __nv_bfloat16 g_oph[(size_t)MR * DI];
__device__ __nv_bfloat16 g_opl[(size_t)MR * DI];
__device__ __nv_bfloat16 g_woh[(size_t)DM * DI];
__device__ __nv_bfloat16 g_wol[(size_t)DM * DI];

// ============================================================================
// PTX helpers (portable sm_80+ subset only — NO tcgen05 on this build target)
// ============================================================================
__device__ __forceinline__ uint32_t smem_u32(const void* p) {
    uint32_t a;
    asm("{ .reg .u64 t; cvta.to.shared.u64 t, %1; cvt.u32.u64 %0, t; }" : "=r"(a) : "l"(p));
    return a;
}
__device__ __forceinline__ void cp_async16(uint32_t dst, const void* src) {
    asm volatile("cp.async.cg.shared.global [%0], [%1], 16;" :: "r"(dst), "l"(src));
}
__device__ __forceinline__ void cp_commit() { asm volatile("cp.async.commit_group;"); }
template<int N> __device__ __forceinline__ void cp_wait() {
    asm volatile("cp.async.wait_group %0;" :: "n"(N));
}
__device__ __forceinline__ void ldmx4(uint32_t& r0, uint32_t& r1, uint32_t& r2, uint32_t& r3,
                                      uint32_t addr) {
    asm volatile("ldmatrix.sync.aligned.m8n8.x4.shared.b16 {%0,%1,%2,%3}, [%4];"
                 : "=r"(r0), "=r"(r1), "=r"(r2), "=r"(r3) : "r"(addr));
}
__device__ __forceinline__ void mma_bf16(float* c, const uint32_t* a, const uint32_t* b) {
    asm volatile(
        "mma.sync.aligned.m16n8k16.row.col.f32.bf16.bf16.f32 "
        "{%0,%1,%2,%3}, {%4,%5,%6,%7}, {%8,%9}, {%0,%1,%2,%3};"
        : "+f"(c[0]), "+f"(c[1]), "+f"(c[2]), "+f"(c[3])
        : "r"(a[0]), "r"(a[1]), "r"(a[2]), "r"(a[3]), "r"(b[0]), "r"(b[1]));
}
// SW64 swizzle on byte offsets within a (128-row x 64B) tile. 16B-granular.
__device__ __forceinline__ uint32_t swz64(uint32_t off) {
    return off ^ ((off >> 3) & 0x30);
}

// ============================================================================
// bf16-split mma.sync GEMM:  C[M,N] = (Ah+Al)[M,K] * (Bh+Bl)[N,K]^T  (fp32 C)
// Block 128x128, BK=32, 8 warps (2x4), warp tile 64x32.
// SW64-swizzled 64B rows; 3-stage cp.async pipeline; ONE barrier per chunk.
// ============================================================================
constexpr int ROWB   = 64;                  // row bytes (32 bf16, no pad - swizzled)
constexpr int TILEB  = 128 * ROWB;          // 8192 per operand tile
constexpr int STAGEB = 4 * TILEB;           // Ah, Al, Bh, Bl = 32768
constexpr int NSTAGE = 3;
constexpr int GEMM_SMEM = NSTAGE * STAGEB;  // 98304

template<int Ktot>
__device__ __forceinline__ void load_stage(uint32_t stage, int k0, int bm0, int bn0,
                                           const __nv_bfloat16* __restrict__ Ah,
                                           const __nv_bfloat16* __restrict__ Al,
                                           const __nv_bfloat16* __restrict__ Bh,
                                           const __nv_bfloat16* __restrict__ Bl,
                                           int tid) {
    const __nv_bfloat16* srcs[4] = {Ah, Al, Bh, Bl};
    const int row0s[2] = {bm0, bn0};
    #pragma unroll
    for (int i = 0; i < 8; i++) {
        int u = tid + i * 256;          // [0, 2048)
        int s = u >> 9;                 // operand section
        int v = u & 511;
        int r = v >> 2, c = v & 3;
        cp_async16(stage + s * TILEB + swz64(r * ROWB + c * 16),
                   srcs[s] + (size_t)(row0s[s >> 1] + r) * Ktot + k0 + c * 8);
    }
    cp_commit();
}

template<int Ntot, int Ktot>
__global__ void __launch_bounds__(256) gemm_mma(const __nv_bfloat16* __restrict__ Ah,
                                                const __nv_bfloat16* __restrict__ Al,
                                                const __nv_bfloat16* __restrict__ Bh,
                                                const __nv_bfloat16* __restrict__ Bl,
                                                float* __restrict__ C) {
    extern __shared__ char smem[];
    const uint32_t sb = smem_u32(smem);
    const int tid  = threadIdx.x;
    const int wid  = tid >> 5, lane = tid & 31;
    const int wm   = wid >> 2;          // 0..1  (M)
    const int wn   = wid & 3;           // 0..3  (N)
    const int bm0  = blockIdx.y * 128;
    const int bn0  = blockIdx.x * 128;
    constexpr int NCHUNK = Ktot / 32;

    float acc[4][4][4];
    #pragma unroll
    for (int i = 0; i < 4; i++)
        #pragma unroll
        for (int j = 0; j < 4; j++)
            #pragma unroll
            for (int q = 0; q < 4; q++) acc[i][j][q] = 0.f;

    // ldmatrix per-lane address components
    const int lrow  = lane & 15;
    const int khalf = (lane >> 4) * 16;   // 16B half select within a 32B k-slab
    const uint32_t aRow = (wm * 64 + lrow) * ROWB;
    const uint32_t bRow = (wn * 32 + lrow) * ROWB;

    load_stage<Ktot>(sb, 0, bm0, bn0, Ah, Al, Bh, Bl, tid);
    load_stage<Ktot>(sb + STAGEB, 32, bm0, bn0, Ah, Al, Bh, Bl, tid);

    uint32_t stOff = 0;                 // compute buffer offset
    uint32_t ldOff = 2 * STAGEB;        // next load buffer offset

    for (int k = 0; k < NCHUNK; k++) {
        if (k + 1 < NCHUNK) cp_wait<1>(); else cp_wait<0>();
        __syncthreads();        // also proves all warps left stage (k-1)%3

        const uint32_t st = sb + stOff;
        #pragma unroll
        for (int kk = 0; kk < 32; kk += 16) {
            const uint32_t kbyte = kk * 2 + khalf;
            // B fragments (hi + lo): 2 x ldmatrix.x4 covers 32 n-rows
            uint32_t bh[8], bl[8];
            #pragma unroll
            for (int nj = 0; nj < 2; nj++) {
                uint32_t a = st + 2 * TILEB + swz64(bRow + nj * 16 * ROWB + kbyte);
                ldmx4(bh[nj * 4 + 0], bh[nj * 4 + 1], bh[nj * 4 + 2], bh[nj * 4 + 3], a);
                ldmx4(bl[nj * 4 + 0], bl[nj * 4 + 1], bl[nj * 4 + 2], bl[nj * 4 + 3], a + TILEB);
            }
            // per m-tile: load A frags then immediately consume -> short live ranges,
            // next mi's LDSM overlaps current mi's HMMAs
            #pragma unroll
            for (int mi = 0; mi < 4; mi++) {
                uint32_t ah[4], al[4];
                uint32_t a = st + swz64(aRow + mi * 16 * ROWB + kbyte);
                ldmx4(ah[0], ah[1], ah[2], ah[3], a);
                ldmx4(al[0], al[1], al[2], al[3], a + TILEB);
                #pragma unroll
                for (int ni = 0; ni < 4; ni++) {
                    const int g = (ni >> 1) * 4 + (ni & 1);
                    uint32_t bhp[2] = {bh[g], bh[g + 2]};
                    uint32_t blp[2] = {bl[g], bl[g + 2]};
                    mma_bf16(acc[mi][ni], ah, bhp);
                    mma_bf16(acc[mi][ni], ah, blp);
                    mma_bf16(acc[mi][ni], al, bhp);
                }
            }
        }
        // issue next stage load AFTER compute; top-of-loop barrier of this
        // iteration guarantees stage (k+2)%3's previous readers are done.
        if (k + 2 < NCHUNK) {
            load_stage<Ktot>(sb + ldOff, (k + 2) * 32, bm0, bn0, Ah, Al, Bh, Bl, tid);
            ldOff += STAGEB; if (ldOff == NSTAGE * STAGEB) ldOff = 0;
        }
        stOff += STAGEB; if (stOff == NSTAGE * STAGEB) stOff = 0;
    }

    // epilogue: fp32 direct to global
    #pragma unroll
    for (int mi = 0; mi < 4; mi++) {
        const int r0 = bm0 + wm * 64 + mi * 16 + (lane >> 2);
        #pragma unroll
        for (int ni = 0; ni < 4; ni++) {
            const int c = bn0 + wn * 32 + ni * 8 + (lane & 3) * 2;
            *(float2*)(C + (size_t)r0 * Ntot + c) =
                make_float2(acc[mi][ni][0], acc[mi][ni][1]);
            *(float2*)(C + (size_t)(r0 + 8) * Ntot + c) =
                make_float2(acc[mi][ni][2], acc[mi][ni][3]);
        }
    }
}

// ============================================================================
// fp32 -> bf16 hi/lo split (4 elements / thread)
// ============================================================================
__global__ void __launch_bounds__(256) split_kernel(const float* __restrict__ in,
                                                    __nv_bfloat16* __restrict__ hi,
                                                    __nv_bfloat16* __restrict__ lo,
                                                    int n4) {
    int i = blockIdx.x * 256 + threadIdx.x;
    if (i >= n4) return;
    float4 v = *(const float4*)(in + (size_t)i * 4);
    float vv[4] = {v.x, v.y, v.z, v.w};
    __nv_bfloat16 h[4], l[4];
    #pragma unroll
    for (int q = 0; q < 4; q++) {
        h[q] = __float2bfloat16(vv[q]);
        l[q] = __float2bfloat16(vv[q] - __bfloat162float(h[q]));
    }
    *(uint2*)(hi + (size_t)i * 4) = *(uint2*)h;
    *(uint2*)(lo + (size_t)i * 4) = *(uint2*)l;
}

// ============================================================================
// causal depthwise conv (k=4, pad left 3) + bias + silu
// ============================================================================
__global__ void __launch_bounds__(256) conv_silu_kernel(const float* __restrict__ conv_w,
                                                        const float* __restrict__ conv_b) {
    int idx = blockIdx.x * 256 + threadIdx.x;
    if (idx >= MR * DI) return;
    int c = idx & (DI - 1);
    int m = idx >> 11;
    int l = m & (LL - 1);

    float4 w4 = *(const float4*)(conv_w + c * 4);
    float w[4] = {w4.x, w4.y, w4.z, w4.w};
    const float* base = g_xz + (size_t)m * NXZ + c;
    float s = conv_b[c];
    #pragma unroll
    for (int t = 0; t < 4; t++) {
        int ll = l - 3 + t;
        if (ll >= 0) s += base[(ptrdiff_t)(t - 3) * NXZ] * w[t];
    }
    float sv = s * (1.f / (1.f + __expf(-s)));
    g_xiconv[idx] = sv;
}

// ============================================================================
// xd = xi_conv @ W_x^T  (N=33). 8 rows/block (64KB dyn smem) halves the
// L2-resident W_x re-read traffic; each warp does 4 n-columns at once.
// ============================================================================
constexpr int PRJ_ROWS = 8;
constexpr int PRJ_SMEM = PRJ_ROWS * DI * 4;   // 65536

__global__ void __launch_bounds__(256) projx_kernel(const float* __restrict__ W_x) {
    extern __shared__ float xs[];             // [PRJ_ROWS][DI]
    const int m0 = blockIdx.x * PRJ_ROWS;
    {
        const float4* src = (const float4*)(g_xiconv + (size_t)m0 * DI);
        float4* dst = (float4*)xs;
        for (int i = threadIdx.x; i < PRJ_ROWS * DI / 4; i += 256) dst[i] = src[i];
    }
    __syncthreads();

    const int warp = threadIdx.x >> 5;
    const int lane = threadIdx.x & 31;
    for (int g = warp; g < 9; g += 8) {
        const int nbase = g * 4;
        const int ncnt  = (g == 8) ? 1 : 4;
        float acc[4][PRJ_ROWS];
        #pragma unroll
        for (int a = 0; a < 4; a++)
            #pragma unroll
            for (int r = 0; r < PRJ_ROWS; r++) acc[a][r] = 0.f;

        for (int k = lane * 4; k < DI; k += 128) {
            float4 xr[PRJ_ROWS];
            #pragma unroll
            for (int r = 0; r < PRJ_ROWS; r++) xr[r] = *(const float4*)&xs[r * DI + k];
            for (int nn = 0; nn < ncnt; nn++) {
                float4 wv = *(const float4*)(W_x + (size_t)(nbase + nn) * DI + k);
                #pragma unroll
                for (int r = 0; r < PRJ_ROWS; r++) {
                    acc[nn][r] += wv.x * xr[r].x + wv.y * xr[r].y
                                + wv.z * xr[r].z + wv.w * xr[r].w;
                }
            }
        }
        for (int nn = 0; nn < ncnt; nn++) {
            #pragma unroll
            for (int r = 0; r < PRJ_ROWS; r++) {
                float v = acc[nn][r];
                #pragma unroll
                for (int off = 16; off; off >>= 1)
                    v += __shfl_xor_sync(0xffffffffu, v, off);
                acc[nn][r] = v;
            }
            if (lane == 0) {
                const int n = nbase + nn;
                #pragma unroll
                for (int r = 0; r < PRJ_ROWS; r++) {
                    int m = m0 + r;
                    if (n == 0)            g_dtraw[m] = acc[nn][r];
                    else if (n < 1 + DS)   g_Bc[m * DS + (n - 1)] = acc[nn][r];
                    else                   g_Cc[m * DS + (n - 1 - DS)] = acc[nn][r];
                }
            }
        }
    }
}

// ============================================================================
// selective scan with fused dt: 8 threads per (b,d) channel, 2 states each,
// 8-deep prefetch. 65536 threads -> ~14 warps/SM for latency hiding.
// ============================================================================
__global__ void __launch_bounds__(256) scan_kernel(const float* __restrict__ A_log,
                                                   const float* __restrict__ W_dt,
                                                   const float* __restrict__ b_dt) {
    const int sub  = threadIdx.x & 7;       // 8 subs per channel
    const int dloc = threadIdx.x >> 3;      // 32 channels per block
    const int d    = blockIdx.x * 32 + dloc;
    const int b    = blockIdx.y;
    const int s0   = sub * 2;

    float Ac[2];
    #pragma unroll
    for (int i = 0; i < 2; i++) Ac[i] = -__expf(fminf(A_log[s0 + i], 5.f));
    const float Wd = W_dt[d];
    const float bd = b_dt[d];

    float h[2] = {0.f, 0.f};

    const size_t mbase = (size_t)b * LL;
    constexpr int PF = 8;
    float  dr_b[PF], xv_b[PF];
    float2 Bv_b[PF], Cv_b[PF];
    #pragma unroll
    for (int u = 0; u < PF; u++) {
        size_t m = mbase + u;
        dr_b[u] = g_dtraw[m];
        xv_b[u] = g_xiconv[m * DI + d];
        Bv_b[u] = *(const float2*)(g_Bc + m * DS + s0);
        Cv_b[u] = *(const float2*)(g_Cc + m * DS + s0);
    }

    for (int l0 = 0; l0 < LL; l0 += PF) {
        #pragma unroll
        for (int u = 0; u < PF; u++) {
            const int l = l0 + u;
            const float  dr = dr_b[u], xv = xv_b[u];
            const float2 Bq = Bv_b[u], Cq = Cv_b[u];

            const int lp = l + PF;
            if (lp < LL) {
                size_t mp = mbase + lp;
                dr_b[u] = g_dtraw[mp];
                xv_b[u] = g_xiconv[mp * DI + d];
                Bv_b[u] = *(const float2*)(g_Bc + mp * DS + s0);
                Cv_b[u] = *(const float2*)(g_Cc + mp * DS + s0);
            }

            // fused softplus dt (off the h->h dependency chain)
            float xx = dr * Wd + bd;
            float sp = fmaxf(xx, 0.f) + __logf(1.f + __expf(-fabsf(xx)));
            float dt = fminf(fmaxf(sp, 1e-4f), 10.f);

            float Bv[2] = {Bq.x, Bq.y};
            float Cv[2] = {Cq.x, Cq.y};
            float y = 0.f;
            #pragma unroll
            for (int i = 0; i < 2; i++) {
                float dA  = __expf(fmaxf(fminf(dt * Ac[i], 0.f), -20.f));
                float dBu = fminf(fmaxf(dt * Bv[i] * xv, -10.f), 10.f);
                h[i] = fminf(fmaxf(h[i] * dA + dBu, -100.f), 100.f);
                y += h[i] * Cv[i];
            }
            y += __shfl_xor_sync(0xffffffffu, y, 1);
            y += __shfl_xor_sync(0xffffffffu, y, 2);
            y += __shfl_xor_sync(0xffffffffu, y, 4);
            if (sub == 0) g_y[(mbase + l) * DI + d] = y;
        }
    }
}

// ============================================================================
// layernorm(y) -> (yn + D*xi) * silu(z) -> bf16 hi/lo. y row cached in regs.
// ============================================================================
__device__ __forceinline__ float block_reduce_sum(float v) {
    __shared__ float sh[8];
    __syncthreads();
    int lane = threadIdx.x & 31, w = threadIdx.x >> 5;
    #pragma unroll
    for (int o = 16; o; o >>= 1) v += __shfl_xor_sync(0xffffffffu, v, o);
    if (lane == 0) sh[w] = v;
    __syncthreads();
    if (threadIdx.x < 32) {
        v = (threadIdx.x < 8) ? sh[threadIdx.x] : 0.f;
        #pragma unroll
        for (int o = 4; o; o >>= 1) v += __shfl_xor_sync(0xffffffffu, v, o);
        if (threadIdx.x == 0) sh[0] = v;
    }
    __syncthreads();
    return sh[0];
}

__global__ void __launch_bounds__(256) lncomb_kernel(const float* __restrict__ ln_w,
                                                     const float* __restrict__ ln_b,
                                                     const float* __restrict__ D_param) {
    const int m = blockIdx.x;
    const float* yrow = g_y + (size_t)m * DI;

    // load 8 y values per thread into registers, single global pass
    float4 yv[2];
    float s = 0.f;
    #pragma unroll
    for (int j = 0; j < 2; j++) {
        yv[j] = *(const float4*)(yrow + j * 1024 + threadIdx.x * 4);
        s += yv[j].x + yv[j].y + yv[j].z + yv[j].w;
    }
    float mu = block_reduce_sum(s) * (1.f / DI);

    float v = 0.f;
    #pragma unroll
    for (int j = 0; j < 2; j++) {
        float t0 = yv[j].x - mu, t1 = yv[j].y - mu, t2 = yv[j].z - mu, t3 = yv[j].w - mu;
        v += t0 * t0 + t1 * t1 + t2 * t2 + t3 * t3;
    }
    float var = block_reduce_sum(v) * (1.f / DI);
    float rstd = rsqrtf(var + 1e-5f);

    #pragma unroll
    for (int j = 0; j < 2; j++) {
        const int dd = j * 1024 + threadIdx.x * 4;
        float4 lw = *(const float4*)(ln_w + dd);
        float4 lb = *(const float4*)(ln_b + dd);
        float4 Dp = *(const float4*)(D_param + dd);
        float4 xi = *(const float4*)(g_xiconv + (size_t)m * DI + dd);
        float4 zz = *(const float4*)(g_xz + (size_t)m * NXZ + DI + dd);
        float yy[4] = {yv[j].x, yv[j].y, yv[j].z, yv[j].w};
        float lww[4] = {lw.x, lw.y, lw.z, lw.w};
        float lbb[4] = {lb.x, lb.y, lb.z, lb.w};
        float dpp[4] = {Dp.x, Dp.y, Dp.z, Dp.w};
        float xii[4] = {xi.x, xi.y, xi.z, xi.w};
        float zzz[4] = {zz.x, zz.y, zz.z, zz.w};
        __nv_bfloat16 hh[4], ll[4];
        #pragma unroll
        for (int q = 0; q < 4; q++) {
            float yn = (yy[q] - mu) * rstd * lww[q] + lbb[q];
            float sz = zzz[q] * (1.f / (1.f + __expf(-zzz[q])));
            float val = (yn + dpp[q] * xii[q]) * sz;
            hh[q] = __float2bfloat16(val);
            ll[q] = __float2bfloat16(val - __bfloat162float(hh[q]));
        }
        *(uint2*)(g_oph + (size_t)m * DI + dd) = *(uint2*)hh;
        *(uint2*)(g_opl + (size_t)m * DI + dd) = *(uint2*)ll;
    }
}

// ============================================================================
// launch
// ============================================================================
extern "C" void kernel_launch(void* const* d_in, const int* in_sizes, int n_in,
                              void* d_out, int out_size) {
    (void)in_sizes; (void)n_in; (void)out_size;
    const float* x       = (const float*)d_in[0];
    const float* W_in    = (const float*)d_in[1];
    const float* conv_w  = (const float*)d_in[2];
    const float* conv_b  = (const float*)d_in[3];
    const float* W_x     = (const float*)d_in[4];
    const float* W_dt    = (const float*)d_in[5];
    const float* b_dt    = (const float*)d_in[6];
    const float* A_log   = (const float*)d_in[7];
    const float* D_param = (const float*)d_in[8];
    const float* W_out   = (const float*)d_in[9];
    const float* ln_w    = (const float*)d_in[10];
    const float* ln_b    = (const float*)d_in[11];
    float* out = (float*)d_out;

    static __nv_bfloat16 *p_xh = nullptr, *p_xl, *p_wih, *p_wil, *p_oph, *p_opl, *p_woh, *p_wol;
    static float *p_xz = nullptr;
    if (!p_xh) {
        cudaGetSymbolAddress((void**)&p_xh,  g_xh);
        cudaGetSymbolAddress((void**)&p_xl,  g_xl);
        cudaGetSymbolAddress((void**)&p_wih, g_wih);
        cudaGetSymbolAddress((void**)&p_wil, g_wil);
        cudaGetSymbolAddress((void**)&p_oph, g_oph);
        cudaGetSymbolAddress((void**)&p_opl, g_opl);
        cudaGetSymbolAddress((void**)&p_woh, g_woh);
        cudaGetSymbolAddress((void**)&p_wol, g_wol);
        cudaGetSymbolAddress((void**)&p_xz,  g_xz);
        cudaFuncSetAttribute(gemm_mma<NXZ, DM>,
                             cudaFuncAttributeMaxDynamicSharedMemorySize, GEMM_SMEM);
        cudaFuncSetAttribute(gemm_mma<DM, DI>,
                             cudaFuncAttributeMaxDynamicSharedMemorySize, GEMM_SMEM);
        cudaFuncSetAttribute(projx_kernel,
                             cudaFuncAttributeMaxDynamicSharedMemorySize, PRJ_SMEM);
    }

    // 0) fp32 -> bf16 hi/lo splits
    split_kernel<<<(MR * DM / 4 + 255) / 256, 256>>>(x, p_xh, p_xl, MR * DM / 4);
    split_kernel<<<(NXZ * DM / 4 + 255) / 256, 256>>>(W_in, p_wih, p_wil, NXZ * DM / 4);
    split_kernel<<<(DM * DI / 4 + 255) / 256, 256>>>(W_out, p_woh, p_wol, DM * DI / 4);

    // 1) xz = x @ W_in^T   (mma.sync, bf16-split)
    {
        dim3 grid(NXZ / 128, MR / 128);
        gemm_mma<NXZ, DM><<<grid, 256, GEMM_SMEM>>>(p_xh, p_xl, p_wih, p_wil, p_xz);
    }
    // 2) conv + silu
    conv_silu_kernel<<<(MR * DI) / 256, 256>>>(conv_w, conv_b);
    // 3) xd projection (dtraw, B, C)
    projx_kernel<<<MR / PRJ_ROWS, 256, PRJ_SMEM>>>(W_x);
    // 4) sequential selective scan (dt fused)
    {
        dim3 grid(DI / 32, BB);
        scan_kernel<<<grid, 256>>>(A_log, W_dt, b_dt);
    }
    // 5) layernorm + combine (writes bf16 hi/lo outpre)
    lncomb_kernel<<<MR, 256>>>(ln_w, ln_b, D_param);
    // 6) out = outpre @ W_out^T   (mma.sync, bf16-split)
    {
        dim3 grid(DM / 128, MR / 128);
        gemm_mma<DM, DI><<<grid, 256, GEMM_SMEM>>>(p_oph, p_opl, p_woh, p_wol, out);
    }
}